// round 6
// baseline (speedup 1.0000x reference)
#include <cuda_runtime.h>

// ---------------------------------------------------------------------------
// QuantizationLayer, single-kernel version.
//
// out[b,c,p,x-1] = (1/100) * sum_{events with key (b,p,x)} t * f(t - c/8),
// f = scalar piecewise-linear MLP. Exact node table on a 1/64 grid; bucket
// moments (n, S1, S2 ~ n*h^2/12) give ~3e-6 rel err (budget 1e-3).
//
// ONE kernel, three roles by block/ticket:
//   blocks [0,17):  evaluate f at 129 grid nodes exactly -> g_nodes
//   all blocks:     hist blocks do ONE packed u32 REDG per event
//                   (bits[21:32)=count, bits[0:21)=sum of 10-bit in-bucket t;
//                   2560 keys x 64 buckets = 656KB, L2-resident)
//   last 320 blocks to arrive at g_done: spin until all blocks arrived
//                   (=> all REDGs visible), then reduce 8 keys each
//                   (warp-per-key, 2 buckets/lane), re-zero hist rows, and
//                   reset counters for the next graph replay. Deterministic.
// ---------------------------------------------------------------------------

#define C_BINS   9
#define H_DIM    80
#define HID_N    100
#define NB       64               // t buckets (width 1/64; c/8 shift = 8 buckets)
#define NNODES   (2*NB + 1)       // 129 nodes covering s in [-1, 1]
#define NKEYS    2560             // B(16) * 2 * H(80)
#define MLPB     17               // blocks doing the MLP node table (17*8 >= 129)
#define EVPT     4                // events per thread in hist part
#define REDUCERS 320              // NKEYS / 8

__device__ unsigned g_hist[NKEYS * NB];   // zero-initialized at module load
__device__ float    g_nodes[NNODES];
__device__ unsigned g_done = 0;           // arrival counter (reset each launch)
__device__ unsigned g_fin  = 0;           // reducer-completion counter

__global__ void __launch_bounds__(256) mega_kernel(
    const float4* __restrict__ ev, int nev,
    const float* __restrict__ W1, const float* __restrict__ b1,
    const float* __restrict__ W2, const float* __restrict__ b2,
    const float* __restrict__ W3, const float* __restrict__ b3,
    float* __restrict__ out, int total)
{
    __shared__ float    h1s[8][HID_N];
    __shared__ float    wsum[4][8];
    __shared__ float    gs[NNODES];
    __shared__ unsigned s_ticket;
    const int tid = threadIdx.x;

    if (blockIdx.x < MLPB) {
        // ---- MLP node evaluation: 8 nodes per block, thread j owns hidden j
        const int NPB = 8;
        const int j = tid;
        const int node0 = blockIdx.x * NPB;
        const float hg = 1.0f / (float)NB;

        if (j < HID_N) {
            float w1 = W1[j], bb1 = b1[j];
            #pragma unroll
            for (int n = 0; n < NPB; n++) {
                float s = (float)(node0 + n - NB) * hg;
                float z = fmaf(s, w1, bb1);
                h1s[n][j] = (z >= 0.0f) ? z : 0.1f * z;
            }
        }
        __syncthreads();

        if (j < 128) {
            float acc[NPB];
            if (j < HID_N) {
                float bb2 = b2[j];
                #pragma unroll
                for (int n = 0; n < NPB; n++) acc[n] = bb2;
                for (int k = 0; k < HID_N; k++) {
                    float w = W2[k * HID_N + j];
                    #pragma unroll
                    for (int n = 0; n < NPB; n++)
                        acc[n] = fmaf(h1s[n][k], w, acc[n]);
                }
                float w3 = W3[j];
                #pragma unroll
                for (int n = 0; n < NPB; n++) {
                    float h2 = (acc[n] >= 0.0f) ? acc[n] : 0.1f * acc[n];
                    acc[n] = h2 * w3;
                }
            } else {
                #pragma unroll
                for (int n = 0; n < NPB; n++) acc[n] = 0.0f;
            }
            #pragma unroll
            for (int n = 0; n < NPB; n++) {
                float v = acc[n];
                #pragma unroll
                for (int o = 16; o > 0; o >>= 1)
                    v += __shfl_down_sync(0xffffffffu, v, o);
                if ((j & 31) == 0) wsum[j >> 5][n] = v;
            }
        }
        __syncthreads();
        if (j < 8) {
            int node = node0 + j;
            if (node < NNODES) {
                float t = wsum[0][j] + wsum[1][j] + wsum[2][j] + wsum[3][j];
                g_nodes[node] = t + b3[0];
            }
        }
    } else {
        // ---- histogram: one packed REDG per event ---------------------------
        int base = (blockIdx.x - MLPB) * (256 * EVPT) + tid;
        #pragma unroll
        for (int u = 0; u < EVPT; u++) {
            int i = base + u * 256;
            if (i < nev) {
                float4 e = ev[i];             // x, t, p, b (exact small ints + t)
                float keyf = fmaf(e.w, 160.0f, fmaf(e.z, 80.0f, e.x)) - 1.0f;
                int key = (int)keyf;
                // bucket (6b) + in-bucket frac (10b) from one convert
                int q = (int)(e.y * 65536.0f);
                int jb = q >> 10;
                if (jb > NB - 1) jb = NB - 1;
                unsigned tq = (unsigned)q & 1023u;
                unsigned pkt = (1u << 21) | tq;
                atomicAdd(&g_hist[(key << 6) + jb], pkt);   // RED.E.ADD
            }
        }
    }

    // ---- arrival: last REDUCERS blocks to finish become reducer blocks ------
    __syncthreads();
    __threadfence();
    if (tid == 0) s_ticket = atomicAdd(&g_done, 1u);
    __syncthreads();
    const int ticket = (int)s_ticket;
    if (ticket < total - REDUCERS) return;
    const int reduceIdx = ticket - (total - REDUCERS);

    // spin until every block has arrived (=> all REDGs globally visible)
    if (tid == 0) {
        while (atomicAdd(&g_done, 0u) < (unsigned)total) __nanosleep(64);
    }
    __syncthreads();

    // ---- reduce: warp per key, 2 buckets/lane, smem node table --------------
    if (tid < NNODES) gs[tid] = g_nodes[tid];
    __syncthreads();

    const int lane = tid & 31;
    const int warp = tid >> 5;
    const int key  = reduceIdx * 8 + warp;
    const unsigned FULL = 0xffffffffu;
    const float hg = 1.0f / (float)NB;

    float acc[C_BINS];
    #pragma unroll
    for (int i = 0; i < C_BINS; i++) acc[i] = 0.0f;

    unsigned* __restrict__ hrow = &g_hist[key * NB];

    unsigned pkt[2];
    #pragma unroll
    for (int s = 0; s < 2; s++) pkt[s] = __ldcg(&hrow[lane + 32 * s]);
    #pragma unroll
    for (int s = 0; s < 2; s++) hrow[lane + 32 * s] = 0u;   // re-zero for replay

    #pragma unroll
    for (int s = 0; s < 2; s++) {
        const int j = lane + 32 * s;
        const float fj = (float)j;
        float fn  = (float)(pkt[s] >> 21);
        float stq = (float)(pkt[s] & 0x1FFFFFu);
        float S1 = hg * fmaf(fn, fj, (stq + 0.5f * fn) * (1.0f / 1024.0f));
        float c  = (fj + 0.5f) * hg;
        float S2 = c * fmaf(-fn, c, 2.0f * S1) + fn * (hg * hg / 12.0f);
        float U  = (S2 - fj * hg * S1) * (float)NB;   // right-node weight
        float V1 = S1 - U;                            // left-node weight
        #pragma unroll
        for (int i = 0; i < C_BINS; i++) {
            int m = j - 8 * i + 64;                   // in [0,127]
            acc[i] = fmaf(gs[m], V1, fmaf(gs[m + 1], U, acc[i]));
        }
    }

    #pragma unroll
    for (int i = 0; i < C_BINS; i++) {
        float v = acc[i];
        #pragma unroll
        for (int o = 16; o > 0; o >>= 1)
            v += __shfl_xor_sync(FULL, v, o);
        acc[i] = v;
    }

    if (lane < C_BINS) {
        int bb = key / 160;
        int rr = key - bb * 160;
        int pp = rr / 80;
        int x1 = rr - pp * 80;
        out[bb * (C_BINS * 2 * H_DIM) + lane * (2 * H_DIM) + pp * H_DIM + x1] =
            acc[lane] * 0.01f;
    }

    // ---- reset counters for the next graph replay ----------------------------
    __syncthreads();
    if (tid == 0) {
        unsigned f = atomicAdd(&g_fin, 1u);
        if (f == REDUCERS - 1) {          // last reducer: everyone else is done
            g_done = 0u;
            g_fin  = 0u;
            __threadfence();
        }
    }
}

// ---- launcher ---------------------------------------------------------------
extern "C" void kernel_launch(void* const* d_in, const int* in_sizes, int n_in,
                              void* d_out, int out_size)
{
    const float* events = (const float*)d_in[0];
    const float* W1 = (const float*)d_in[1];
    const float* b1 = (const float*)d_in[2];
    const float* W2 = (const float*)d_in[3];
    const float* b2 = (const float*)d_in[4];
    const float* W3 = (const float*)d_in[5];
    const float* b3 = (const float*)d_in[6];

    int nev = in_sizes[0] / 4;
    int gridHist = (nev + 256 * EVPT - 1) / (256 * EVPT);
    int total = MLPB + gridHist;

    mega_kernel<<<total, 256>>>((const float4*)events, nev,
                                W1, b1, W2, b2, W3, b3,
                                (float*)d_out, total);
}

// round 7
// speedup vs baseline: 1.2656x; 1.2656x over previous
#include <cuda_runtime.h>

// ---------------------------------------------------------------------------
// QuantizationLayer: events (x,t,p,b) scattered through a scalar MLP into a
// (B, C, 2H) voxel grid.
//
// out[b,c,p,x-1] = (1/100) * sum_{events with key (b,p,x)} t * f(t - c/8)
// where f = value_mlp is scalar->scalar piecewise linear. Linear interpolant
// on a 1/64 grid approximates f; within-bucket spread handled by moments
// (n, S1, S2 ~ n*h^2/12). rel_err ~3e-6 vs 1e-3 budget.
//
// Launch 1 (fused): blocks [0,17) evaluate f at 129 grid nodes exactly;
//                   remaining blocks: ONE packed u32 REDG per event
//                   (bits[21:32)=count, bits[0:21)=sum of 10-bit in-bucket t;
//                   overflow-safe: 2047*1023 < 2^21). Cell index computed in
//                   one exact FMA chain + single F2I; q=floor(t*2^16) exact.
// Launch 2 (reduce): warp-per-key; 2 buckets/lane; 129-node smem table;
//                   re-zeros hist rows as it reads them (device globals start
//                   zeroed -> every graph replay deterministic).
// ---------------------------------------------------------------------------

#define C_BINS 9
#define H_DIM  80
#define HID_N  100
#define NB     64                // t buckets (width 1/64; c/8 shift = 8 buckets)
#define NNODES (2*NB + 1)        // 129 nodes covering s in [-1, 1]
#define MAXB   16
#define NKEYS  (MAXB * 2 * H_DIM)   // 2560
#define MLPB   17                // blocks doing the MLP node table (17*8 >= 129)
#define EVPT   8                 // events per thread in hist part

__device__ unsigned g_hist[NKEYS * NB];   // zero-initialized at module load
__device__ float    g_nodes[NNODES];

// ---- per-event cell + packet math (exact; see header) ----------------------
__device__ __forceinline__ void hist_one(float4 e) {
    // q = floor(t * 2^16): t in [0,1), *2^16 is exact (power of two) -> q <= 65535
    int q = (int)(e.y * 65536.0f);
    float jbf = (float)(q >> 10);            // bucket index as float (0..63)
    // cell+64 = b*10240 + p*5120 + x*64 + jb   (all terms integer, < 2^24: exact)
    float cellf = fmaf(e.w, 10240.0f, fmaf(e.z, 5120.0f, fmaf(e.x, 64.0f, jbf)));
    int cell = (int)cellf;
    unsigned pkt = ((unsigned)q & 1023u) | (1u << 21);   // single LOP3
    atomicAdd(&g_hist[cell - 64], pkt);      // RED.E.ADD (no return)
}

// ---- fused: MLP node table (blocks < MLPB) + packed histogram (rest) -------
__global__ void __launch_bounds__(256) fused_mlp_hist_kernel(
    const float4* __restrict__ ev, int nev,
    const float* __restrict__ W1, const float* __restrict__ b1,
    const float* __restrict__ W2, const float* __restrict__ b2,
    const float* __restrict__ W3, const float* __restrict__ b3)
{
    if (blockIdx.x < MLPB) {
        // ---- MLP node evaluation: 8 nodes per block, thread j owns hidden j
        const int NPB = 8;
        __shared__ float h1s[NPB][HID_N];
        __shared__ float wsum[4][NPB];
        const int j = threadIdx.x;
        const int node0 = blockIdx.x * NPB;
        const float hg = 1.0f / (float)NB;

        if (j < HID_N) {
            float w1 = W1[j], bb1 = b1[j];
            #pragma unroll
            for (int n = 0; n < NPB; n++) {
                float s = (float)(node0 + n - NB) * hg;
                float z = fmaf(s, w1, bb1);
                h1s[n][j] = (z >= 0.0f) ? z : 0.1f * z;
            }
        }
        __syncthreads();

        if (j < 128) {
            float acc[NPB];
            if (j < HID_N) {
                float bb2 = b2[j];
                #pragma unroll
                for (int n = 0; n < NPB; n++) acc[n] = bb2;
                for (int k = 0; k < HID_N; k++) {
                    float w = W2[k * HID_N + j];
                    #pragma unroll
                    for (int n = 0; n < NPB; n++)
                        acc[n] = fmaf(h1s[n][k], w, acc[n]);
                }
                float w3 = W3[j];
                #pragma unroll
                for (int n = 0; n < NPB; n++) {
                    float h2 = (acc[n] >= 0.0f) ? acc[n] : 0.1f * acc[n];
                    acc[n] = h2 * w3;
                }
            } else {
                #pragma unroll
                for (int n = 0; n < NPB; n++) acc[n] = 0.0f;
            }
            #pragma unroll
            for (int n = 0; n < NPB; n++) {
                float v = acc[n];
                #pragma unroll
                for (int o = 16; o > 0; o >>= 1)
                    v += __shfl_down_sync(0xffffffffu, v, o);
                if ((j & 31) == 0) wsum[j >> 5][n] = v;
            }
        }
        __syncthreads();
        if (j < 8) {
            int node = node0 + j;
            if (node < NNODES) {
                float t = wsum[0][j] + wsum[1][j] + wsum[2][j] + wsum[3][j];
                g_nodes[node] = t + b3[0];
            }
        }
        return;
    }

    // ---- histogram: one packed REDG per event -------------------------------
    const int blk  = blockIdx.x - MLPB;
    const int base = blk * (256 * EVPT) + threadIdx.x;

    if ((blk + 1) * (256 * EVPT) <= nev) {
        // full block: no per-event guards; front-batch the 8 streaming loads
        float4 e[EVPT];
        #pragma unroll
        for (int u = 0; u < EVPT; u++)
            e[u] = __ldcs(&ev[base + u * 256]);
        #pragma unroll
        for (int u = 0; u < EVPT; u++)
            hist_one(e[u]);
    } else {
        #pragma unroll
        for (int u = 0; u < EVPT; u++) {
            int i = base + u * 256;
            if (i < nev) hist_one(__ldcs(&ev[i]));
        }
    }
}

// ---- reduce: warp per key, 2 buckets/lane, smem node table -------------------
__global__ void __launch_bounds__(256) reduce_kernel(float* __restrict__ out)
{
    __shared__ float gs[NNODES];
    const int tid  = threadIdx.x;
    if (tid < NNODES) gs[tid] = g_nodes[tid];
    __syncthreads();

    const int lane = tid & 31;
    const int warp = tid >> 5;
    const int key  = blockIdx.x * 8 + warp;
    const unsigned FULL = 0xffffffffu;

    const float hg = 1.0f / (float)NB;
    float acc[C_BINS];
    #pragma unroll
    for (int i = 0; i < C_BINS; i++) acc[i] = 0.0f;

    unsigned* __restrict__ hrow = &g_hist[key * NB];

    // Load both packed buckets up front, then re-zero for the next replay.
    unsigned pkt[2];
    #pragma unroll
    for (int s = 0; s < 2; s++) pkt[s] = hrow[lane + 32 * s];
    #pragma unroll
    for (int s = 0; s < 2; s++) hrow[lane + 32 * s] = 0u;

    #pragma unroll
    for (int s = 0; s < 2; s++) {
        const int j = lane + 32 * s;
        const float fj = (float)j;
        float fn  = (float)(pkt[s] >> 21);
        float stq = (float)(pkt[s] & 0x1FFFFFu);
        // S1 = sum of t over bucket (dequantized, +0.5 LSB de-bias)
        float S1 = hg * fmaf(fn, fj, (stq + 0.5f * fn) * (1.0f / 1024.0f));
        float c  = (fj + 0.5f) * hg;
        float S2 = c * fmaf(-fn, c, 2.0f * S1) + fn * (hg * hg / 12.0f);
        float U  = (S2 - fj * hg * S1) * (float)NB;  // right-node weight
        float V1 = S1 - U;                           // left-node weight
        #pragma unroll
        for (int i = 0; i < C_BINS; i++) {
            int m = j - 8 * i + 64;                  // in [0,127]
            acc[i] = fmaf(gs[m], V1, fmaf(gs[m + 1], U, acc[i]));
        }
    }

    // warp butterfly reduce each bin
    #pragma unroll
    for (int i = 0; i < C_BINS; i++) {
        float v = acc[i];
        #pragma unroll
        for (int o = 16; o > 0; o >>= 1)
            v += __shfl_xor_sync(FULL, v, o);
        acc[i] = v;
    }

    if (lane < C_BINS) {
        int bb = key / 160;
        int rr = key - bb * 160;
        int pp = rr / 80;
        int x1 = rr - pp * 80;
        out[bb * (C_BINS * 2 * H_DIM) + lane * (2 * H_DIM) + pp * H_DIM + x1] =
            acc[lane] * 0.01f;
    }
}

// ---- launcher ---------------------------------------------------------------
extern "C" void kernel_launch(void* const* d_in, const int* in_sizes, int n_in,
                              void* d_out, int out_size)
{
    const float* events = (const float*)d_in[0];
    const float* W1 = (const float*)d_in[1];
    const float* b1 = (const float*)d_in[2];
    const float* W2 = (const float*)d_in[3];
    const float* b2 = (const float*)d_in[4];
    const float* W3 = (const float*)d_in[5];
    const float* b3 = (const float*)d_in[6];

    int nev = in_sizes[0] / 4;
    int nkeys = out_size / C_BINS;          // B * 2 * H (= 2560 for B=16)

    int gridHist = (nev + 256 * EVPT - 1) / (256 * EVPT);
    fused_mlp_hist_kernel<<<MLPB + gridHist, 256>>>(
        (const float4*)events, nev, W1, b1, W2, b2, W3, b3);
    reduce_kernel<<<nkeys / 8, 256>>>((float*)d_out);
}

// round 8
// speedup vs baseline: 1.3893x; 1.0977x over previous
#include <cuda_runtime.h>

// ---------------------------------------------------------------------------
// QuantizationLayer: events (x,t,p,b) scattered through a scalar MLP into a
// (B, C, 2H) voxel grid.
//
// out[b,c,p,x-1] = (1/100) * sum_{events with key (b,p,x)} t * f(t - c/8)
// where f = value_mlp is scalar->scalar piecewise linear. Linear interpolant
// on a 1/64 grid approximates f; within-bucket spread handled by moments
// (n, S1, S2 ~ n*h^2/12). rel_err ~3e-6 vs 1e-3 budget.
//
// Launch 1 (fused): blocks [0,17) evaluate f at 129 grid nodes exactly;
//                   remaining blocks: ONE packed u32 REDG per event
//                   (bits[21:32)=count, bits[0:21)=sum of 10-bit in-bucket t;
//                   overflow-safe: 2047*1023 < 2^21).
// Launch 2 (reduce): launched with PDL (programmatic stream serialization) so
//                   its launch/ramp overlaps the fused kernel's tail; calls
//                   cudaGridDependencySynchronize() before touching hist.
//                   Warp-per-key; 2 buckets/lane; 129-node smem table;
//                   re-zeros hist rows as it reads them (device globals start
//                   zeroed -> every graph replay deterministic).
// ---------------------------------------------------------------------------

#define C_BINS 9
#define H_DIM  80
#define HID_N  100
#define NB     64                // t buckets (width 1/64; c/8 shift = 8 buckets)
#define NNODES (2*NB + 1)        // 129 nodes covering s in [-1, 1]
#define MAXB   16
#define NKEYS  (MAXB * 2 * H_DIM)   // 2560
#define MLPB   17                // blocks doing the MLP node table (17*8 >= 129)
#define EVPT   4                 // events per thread in hist part

__device__ unsigned g_hist[NKEYS * NB];   // zero-initialized at module load
__device__ float    g_nodes[NNODES];

// ---- per-event cell + packet math (all steps exact) -------------------------
__device__ __forceinline__ void hist_one(float4 e) {
    // q = floor(t * 2^16): t in [0,1), *2^16 exact (power of two) -> q <= 65535
    int q = (int)(e.y * 65536.0f);
    float jbf = (float)(q >> 10);            // bucket index as float (0..63)
    // cell+64 = b*10240 + p*5120 + x*64 + jb  (integers < 2^24: exact in fp32)
    float cellf = fmaf(e.w, 10240.0f, fmaf(e.z, 5120.0f, fmaf(e.x, 64.0f, jbf)));
    int cell = (int)cellf;
    unsigned pkt = ((unsigned)q & 1023u) | (1u << 21);
    atomicAdd(&g_hist[cell - 64], pkt);      // RED.E.ADD (no return)
}

// ---- fused: MLP node table (blocks < MLPB) + packed histogram (rest) -------
__global__ void __launch_bounds__(256) fused_mlp_hist_kernel(
    const float4* __restrict__ ev, int nev,
    const float* __restrict__ W1, const float* __restrict__ b1,
    const float* __restrict__ W2, const float* __restrict__ b2,
    const float* __restrict__ W3, const float* __restrict__ b3)
{
    if (blockIdx.x < MLPB) {
        // ---- MLP node evaluation: 8 nodes per block, thread j owns hidden j
        const int NPB = 8;
        __shared__ float h1s[NPB][HID_N];
        __shared__ float wsum[4][NPB];
        const int j = threadIdx.x;
        const int node0 = blockIdx.x * NPB;
        const float hg = 1.0f / (float)NB;

        if (j < HID_N) {
            float w1 = W1[j], bb1 = b1[j];
            #pragma unroll
            for (int n = 0; n < NPB; n++) {
                float s = (float)(node0 + n - NB) * hg;
                float z = fmaf(s, w1, bb1);
                h1s[n][j] = (z >= 0.0f) ? z : 0.1f * z;
            }
        }
        __syncthreads();

        if (j < 128) {
            float acc[NPB];
            if (j < HID_N) {
                float bb2 = b2[j];
                #pragma unroll
                for (int n = 0; n < NPB; n++) acc[n] = bb2;
                for (int k = 0; k < HID_N; k++) {
                    float w = W2[k * HID_N + j];
                    #pragma unroll
                    for (int n = 0; n < NPB; n++)
                        acc[n] = fmaf(h1s[n][k], w, acc[n]);
                }
                float w3 = W3[j];
                #pragma unroll
                for (int n = 0; n < NPB; n++) {
                    float h2 = (acc[n] >= 0.0f) ? acc[n] : 0.1f * acc[n];
                    acc[n] = h2 * w3;
                }
            } else {
                #pragma unroll
                for (int n = 0; n < NPB; n++) acc[n] = 0.0f;
            }
            #pragma unroll
            for (int n = 0; n < NPB; n++) {
                float v = acc[n];
                #pragma unroll
                for (int o = 16; o > 0; o >>= 1)
                    v += __shfl_down_sync(0xffffffffu, v, o);
                if ((j & 31) == 0) wsum[j >> 5][n] = v;
            }
        }
        __syncthreads();
        if (j < 8) {
            int node = node0 + j;
            if (node < NNODES) {
                float t = wsum[0][j] + wsum[1][j] + wsum[2][j] + wsum[3][j];
                g_nodes[node] = t + b3[0];
            }
        }
        cudaTriggerProgrammaticLaunchCompletion();
        return;
    }

    // ---- histogram: one packed REDG per event (R4 loop shape: low MLP_p1) ---
    int base = (blockIdx.x - MLPB) * (256 * EVPT) + threadIdx.x;
    #pragma unroll
    for (int u = 0; u < EVPT; u++) {
        int i = base + u * 256;
        if (i < nev) hist_one(ev[i]);
    }
    cudaTriggerProgrammaticLaunchCompletion();
}

// ---- reduce: warp per key, 2 buckets/lane, smem node table -------------------
__global__ void __launch_bounds__(256) reduce_kernel(float* __restrict__ out)
{
    __shared__ float gs[NNODES];
    const int tid  = threadIdx.x;
    const int lane = tid & 31;
    const int warp = tid >> 5;
    const int key  = blockIdx.x * 8 + warp;
    const unsigned FULL = 0xffffffffu;
    const float hg = 1.0f / (float)NB;

    // Wait for the fused kernel's memory to be visible (PDL edge), then read.
    cudaGridDependencySynchronize();

    if (tid < NNODES) gs[tid] = g_nodes[tid];
    __syncthreads();

    float acc[C_BINS];
    #pragma unroll
    for (int i = 0; i < C_BINS; i++) acc[i] = 0.0f;

    unsigned* __restrict__ hrow = &g_hist[key * NB];

    // Load both packed buckets up front, then re-zero for the next replay.
    unsigned pkt[2];
    #pragma unroll
    for (int s = 0; s < 2; s++) pkt[s] = hrow[lane + 32 * s];
    #pragma unroll
    for (int s = 0; s < 2; s++) hrow[lane + 32 * s] = 0u;

    #pragma unroll
    for (int s = 0; s < 2; s++) {
        const int j = lane + 32 * s;
        const float fj = (float)j;
        float fn  = (float)(pkt[s] >> 21);
        float stq = (float)(pkt[s] & 0x1FFFFFu);
        // S1 = sum of t over bucket (dequantized, +0.5 LSB de-bias)
        float S1 = hg * fmaf(fn, fj, (stq + 0.5f * fn) * (1.0f / 1024.0f));
        float c  = (fj + 0.5f) * hg;
        float S2 = c * fmaf(-fn, c, 2.0f * S1) + fn * (hg * hg / 12.0f);
        float U  = (S2 - fj * hg * S1) * (float)NB;  // right-node weight
        float V1 = S1 - U;                           // left-node weight
        #pragma unroll
        for (int i = 0; i < C_BINS; i++) {
            int m = j - 8 * i + 64;                  // in [0,127]
            acc[i] = fmaf(gs[m], V1, fmaf(gs[m + 1], U, acc[i]));
        }
    }

    // warp butterfly reduce each bin
    #pragma unroll
    for (int i = 0; i < C_BINS; i++) {
        float v = acc[i];
        #pragma unroll
        for (int o = 16; o > 0; o >>= 1)
            v += __shfl_xor_sync(FULL, v, o);
        acc[i] = v;
    }

    if (lane < C_BINS) {
        int bb = key / 160;
        int rr = key - bb * 160;
        int pp = rr / 80;
        int x1 = rr - pp * 80;
        out[bb * (C_BINS * 2 * H_DIM) + lane * (2 * H_DIM) + pp * H_DIM + x1] =
            acc[lane] * 0.01f;
    }
}

// ---- launcher ---------------------------------------------------------------
extern "C" void kernel_launch(void* const* d_in, const int* in_sizes, int n_in,
                              void* d_out, int out_size)
{
    const float* events = (const float*)d_in[0];
    const float* W1 = (const float*)d_in[1];
    const float* b1 = (const float*)d_in[2];
    const float* W2 = (const float*)d_in[3];
    const float* b2 = (const float*)d_in[4];
    const float* W3 = (const float*)d_in[5];
    const float* b3 = (const float*)d_in[6];

    int nev = in_sizes[0] / 4;
    int nkeys = out_size / C_BINS;          // B * 2 * H (= 2560 for B=16)

    int gridHist = (nev + 256 * EVPT - 1) / (256 * EVPT);
    fused_mlp_hist_kernel<<<MLPB + gridHist, 256>>>(
        (const float4*)events, nev, W1, b1, W2, b2, W3, b3);

    // Reduce with PDL: launch overlaps the fused kernel's tail; the kernel
    // itself gates on cudaGridDependencySynchronize() before reading hist.
    cudaLaunchConfig_t cfg = {};
    cfg.gridDim  = dim3(nkeys / 8, 1, 1);
    cfg.blockDim = dim3(256, 1, 1);
    cfg.dynamicSmemBytes = 0;
    cudaLaunchAttribute attr[1];
    attr[0].id = cudaLaunchAttributeProgrammaticStreamSerialization;
    attr[0].val.programmaticStreamSerializationAllowed = 1;
    cfg.attrs = attr;
    cfg.numAttrs = 1;
    cudaLaunchKernelEx(&cfg, reduce_kernel, (float*)d_out);
}